// round 15
// baseline (speedup 1.0000x reference)
#include <cuda_runtime.h>
#include <cuda_bf16.h>
#include <cstdint>

// ---------------- problem constants ----------------
#define NPMAX   2400000
#define GX      432
#define GY      496
#define NVOX    (GX*GY)        // 214272 (z dim = 1)
#define MAXV    40000
#define MAXP    32
#define CAP     64             // per-voxel bucket capacity (max observed cnt ~35)
#define CHUNK   8192           // points per k_rank block (8/thread, 1024 threads)
#define CHSH    13             // log2(CHUNK)
#define NHIST   512            // >= nb = ceil(NPMAX/CHUNK) = 293
#define SENTINEL 0x7FFFFFFF

// ---------------- device scratch (static: no allocations allowed) ----------------
// Self-resetting state machine: g_cnt zeroed by k_mid, g_hist zeroed by k_emit,
// g_first/g_vlist fully rewritten each call. Load-time zero-init covers call 0.
__device__ int g_first[NVOX];       // packed: min point idx (22 bits) | cnt (6 bits @22)
__device__ int g_cnt[NVOX];         // arrivals per voxel (zeroed by k_mid each call)
__device__ int g_vlist[MAXV];       // slot -> packed (cnt<<18 | lin)
__device__ int g_vbuf[NVOX * CAP];  // per-voxel point indices (unordered set)
__device__ int g_hist[NHIST];       // per-chunk first-occurrence counts (zeroed by k_emit)

// ---------------- voxel coordinate ----------------
// Mirror of XLA's (p - pc_min) * RN(1/voxel_size). RN(1/0.16f)=6.25f exactly;
// RN(1/4)=0.25f. Intrinsics block FMA contraction. (Verified: rel_err == 0.0.)
__device__ __forceinline__ int point_lin(float4 p) {
    float fx = floorf(__fmul_rn(__fsub_rn(p.x,   0.0f), 6.25f));
    float fy = floorf(__fmul_rn(__fsub_rn(p.y, -39.68f), 6.25f));
    float fz = floorf(__fmul_rn(__fsub_rn(p.z,  -3.0f), 0.25f));
    bool valid = (fx >= 0.f) & (fx < (float)GX) &
                 (fy >= 0.f) & (fy < (float)GY) &
                 (fz >= 0.f) & (fz < 1.f);
    if (!valid) return -1;
    return (int)fy * GX + (int)fx;   // z == 0
}

// All 32 lanes of the calling warp MUST execute this (full-mask shuffles).
__device__ __forceinline__ int warpInclScan(int v, int lane) {
    #pragma unroll
    for (int o = 1; o < 32; o <<= 1) {
        int t = __shfl_up_sync(0xffffffffu, v, o);
        if (lane >= o) v += t;
    }
    return v;
}

// ---------------- kernels ----------------
// 1) One atomic + one store per point. No atomicMin: the first-point index is
//    recovered later as min over the (complete, cnt<=CAP) bucket set.
__global__ void k_point(const float4* __restrict__ pts, int n) {
    int i = blockIdx.x * blockDim.x + threadIdx.x;
    if (i >= n) return;
    int lin = point_lin(pts[i]);
    if (lin < 0) return;
    int j = atomicAdd(&g_cnt[lin], 1);
    if (j < CAP) g_vbuf[lin * CAP + j] = i;
}

// 2) Per-voxel: first = min(bucket), pack first|cnt into g_first, histogram
//    first into CHUNK buckets, and reset g_cnt for the next call.
__global__ void k_mid() {
    int v = blockIdx.x * blockDim.x + threadIdx.x;
    if (v >= NVOX) return;
    int c = g_cnt[v];
    g_cnt[v] = 0;                              // self-reset (deterministic replay)
    if (c == 0) { g_first[v] = SENTINEL; return; }
    int cc = min(c, CAP);
    const int4* b4 = (const int4*)&g_vbuf[v * CAP];
    int first = SENTINEL;
    int nq = (cc + 3) >> 2;
    for (int q = 0; q < nq; q++) {             // wide loads: ~2 sectors/voxel
        int4 e = b4[q];
        int j = q * 4;
        if (j     < cc) first = min(first, e.x);
        if (j + 1 < cc) first = min(first, e.y);
        if (j + 2 < cc) first = min(first, e.z);
        if (j + 3 < cc) first = min(first, e.w);
    }
    g_first[v] = first | (cc << 22);           // first < 2^22, cc < 2^6
    atomicAdd(&g_hist[first >> CHSH], 1);
}

// 3) Slot assignment. Each block reduces g_hist[0..bid) (one coalesced load +
//    2 barriers) for its exact offset; blocks past MAXV exit before touching
//    point data (~98%). Active blocks mark-scan their 8192 points from pts.
__global__ void k_rank(const float4* __restrict__ pts, int n,
                       float* __restrict__ o_coor) {
    __shared__ int warpTot[32];
    int tid = threadIdx.x;                     // 1024 threads
    int lane = tid & 31, w = tid >> 5;
    int bid = blockIdx.x;

    // exclusive offset = sum of preceding chunk counts (nb <= 512 <= 1024)
    int v = (tid < bid) ? g_hist[tid] : 0;
    #pragma unroll
    for (int o = 16; o > 0; o >>= 1) v += __shfl_down_sync(0xffffffffu, v, o);
    if (lane == 0) warpTot[w] = v;
    __syncthreads();
    if (w == 0) {
        int t = warpTot[lane];
        #pragma unroll
        for (int o = 16; o > 0; o >>= 1) t += __shfl_down_sync(0xffffffffu, t, o);
        if (lane == 0) warpTot[0] = t;
    }
    __syncthreads();
    int off = warpTot[0];
    if (off >= MAXV) return;
    __syncthreads();                           // warpTot reused below

    int base = bid * CHUNK + tid * 8;
    int lin[8], fw[8], m[8];
    int s = 0;
    #pragma unroll
    for (int k = 0; k < 8; k++) {
        int i = base + k;
        int l = (i < n) ? point_lin(pts[i]) : -1;
        lin[k] = l;
        fw[k] = (l >= 0) ? g_first[l] : SENTINEL;
        m[k] = (l >= 0 && (fw[k] & 0x3FFFFF) == i) ? 1 : 0;   // i < 2^22, != 0x3FFFFF
        s += m[k];
    }

    // block scan: warp shfl scan + 32-lane aggregate scan (2 barriers)
    int inc = warpInclScan(s, lane);
    if (lane == 31) warpTot[w] = inc;
    __syncthreads();
    if (w == 0) warpTot[lane] = warpInclScan(warpTot[lane], lane);
    __syncthreads();
    int ex = inc + ((w > 0) ? warpTot[w - 1] : 0) - s;

    int r = off + ex;
    #pragma unroll
    for (int k = 0; k < 8; k++) {
        if (m[k]) {
            if (r < MAXV) {
                int c = (fw[k] >> 22) & 0x3F;              // clamped count
                g_vlist[r] = lin[k] | (c << 18);           // lin < 2^18
                int x = lin[k] % GX, y = lin[k] / GX;      // z == 0
                o_coor[r * 3 + 0] = 0.0f;
                o_coor[r * 3 + 1] = (float)y;
                o_coor[r * 3 + 2] = (float)x;
            }
            r++;
        }
    }
}

// 4) One warp per slot: rank bucket entries by point index (distinct ->
//    permutation), write rows at their ranks, zero padding rows in-place.
//    Block 0 also zeroes g_hist for the next call.
__global__ void k_emit(const float4* __restrict__ pts,
                       float4* __restrict__ o_vox,
                       float* __restrict__ o_np) {
    if (blockIdx.x == 0) {
        for (int t = threadIdx.x; t < NHIST; t += blockDim.x) g_hist[t] = 0;
    }
    int s = blockIdx.x * 8 + (threadIdx.x >> 5);
    if (s >= MAXV) return;
    int lane = threadIdx.x & 31;
    int v = g_vlist[s];                  // always valid: ~214k hit voxels >= MAXV
    int lin = v & 0x3FFFF;
    int n = (v >> 18) & 0x3F;
    if (lane == 0) o_np[s] = (float)min(n, MAXP);
    float4* row = o_vox + (size_t)s * MAXP;
    const float4 z4 = make_float4(0.f, 0.f, 0.f, 0.f);

    if (n <= 32) {                       // common case
        int m = n;                       // warp-uniform
        const int* buf = &g_vbuf[lin * CAP];
        int e0 = (lane < m) ? buf[lane] : SENTINEL;
        int r0 = 0;
        for (int j = 0; j < m; j++) {
            int a = __shfl_sync(0xffffffffu, e0, j);
            r0 += (a < e0) ? 1 : 0;
        }
        if (lane < m) row[r0] = pts[e0];
        else          row[lane] = z4;    // zero padding rows [m, 32)
    } else {                             // rare: up to 64 entries, keep ranks < 32
        int m = n;
        const int* buf = &g_vbuf[lin * CAP];
        int e0 = (lane      < m) ? buf[lane]      : SENTINEL;
        int e1 = (lane + 32 < m) ? buf[lane + 32] : SENTINEL;
        int r0 = 0, r1 = 0;
        #pragma unroll
        for (int j = 0; j < 32; j++) {
            int a = __shfl_sync(0xffffffffu, e0, j);
            int b = __shfl_sync(0xffffffffu, e1, j);
            r0 += (a < e0) + (b < e0);
            r1 += (a < e1) + (b < e1);
        }
        if (e0 != SENTINEL && r0 < MAXP) row[r0] = pts[e0];
        if (e1 != SENTINEL && r1 < MAXP) row[r1] = pts[e1];
    }
}

// ---------------- launch ----------------
extern "C" void kernel_launch(void* const* d_in, const int* in_sizes, int n_in,
                              void* d_out, int out_size) {
    const float4* pts = (const float4*)d_in[0];
    int n = in_sizes[0] / 4;
    if (n > NPMAX) n = NPMAX;

    float* out    = (float*)d_out;
    float* o_coor = out + (size_t)MAXV * MAXP * 4;   // 5,120,000
    float* o_np   = o_coor + (size_t)MAXV * 3;       // +120,000

    int nb = (n + CHUNK - 1) / CHUNK;                // 293 for n = 2.4M

    k_point<<<(n + 255) / 256, 256>>>(pts, n);
    k_mid  <<<(NVOX + 255) / 256, 256>>>();
    k_rank <<<nb, 1024>>>(pts, n, o_coor);
    k_emit <<<(MAXV + 7) / 8, 256>>>(pts, (float4*)out, o_np);
}

// round 16
// speedup vs baseline: 1.5799x; 1.5799x over previous
#include <cuda_runtime.h>
#include <cuda_bf16.h>
#include <cstdint>

// ---------------- problem constants ----------------
#define NPMAX   2400000
#define GX      432
#define GY      496
#define NVOX    (GX*GY)        // 214272 (z dim = 1)
#define MAXV    40000
#define MAXP    32
#define CAP     64             // per-voxel bucket capacity (max observed cnt ~35)
#define CHUNK   4096           // points per scanrank block (4/thread, 1024 threads)
#define SENTINEL 0x7FFFFFFF

#define FLAG_AGG 1u
#define FLAG_INC 2u

// ---------------- device scratch (static: no allocations allowed) ----------------
__device__ int g_first[NVOX];                 // min original point index per voxel
__device__ int g_cnt[NVOX];                   // total arrivals per voxel
__device__ int g_lin[NPMAX];                  // cached voxel id per point (-1 invalid)
__device__ int g_vlist[MAXV];                 // slot -> packed (cnt<<18 | lin), -1 empty
__device__ int g_vbuf[NVOX * CAP];            // per-voxel point indices (unordered set)
__device__ unsigned long long g_desc[1024];   // decoupled look-back descriptors

// ---------------- voxel coordinate ----------------
// Mirror of XLA's (p - pc_min) * RN(1/voxel_size). RN(1/0.16f)=6.25f exactly;
// RN(1/4)=0.25f. Intrinsics block FMA contraction. (Verified: rel_err == 0.0.)
__device__ __forceinline__ int point_lin(float4 p) {
    float fx = floorf(__fmul_rn(__fsub_rn(p.x,   0.0f), 6.25f));
    float fy = floorf(__fmul_rn(__fsub_rn(p.y, -39.68f), 6.25f));
    float fz = floorf(__fmul_rn(__fsub_rn(p.z,  -3.0f), 0.25f));
    bool valid = (fx >= 0.f) & (fx < (float)GX) &
                 (fy >= 0.f) & (fy < (float)GY) &
                 (fz >= 0.f) & (fz < 1.f);
    if (!valid) return -1;
    return (int)fy * GX + (int)fx;   // z == 0
}

// All 32 lanes of the calling warp MUST execute this (full-mask shuffles).
__device__ __forceinline__ int warpInclScan(int v, int lane) {
    #pragma unroll
    for (int o = 1; o < 32; o <<= 1) {
        int t = __shfl_up_sync(0xffffffffu, v, o);
        if (lane >= o) v += t;
    }
    return v;
}

// ---------------- kernels ----------------
__global__ void k_init(float* __restrict__ o_coor) {
    int i = blockIdx.x * blockDim.x + threadIdx.x;
    if (i < NVOX) { g_first[i] = SENTINEL; g_cnt[i] = 0; }
    if (i < MAXV)  g_vlist[i] = -1;
    if (i < MAXV * 3) o_coor[i] = -1.0f;
    if (i < 1024)  g_desc[i] = 0ull;
}

__global__ void k_point(const float4* __restrict__ pts, int n) {
    int i = blockIdx.x * blockDim.x + threadIdx.x;
    if (i >= n) return;
    int lin = point_lin(pts[i]);
    g_lin[i] = lin;
    if (lin < 0) return;
    atomicMin(&g_first[lin], i);               // fire-and-forget RED.MIN
    int j = atomicAdd(&g_cnt[lin], 1);
    if (j < CAP) g_vbuf[lin * CAP + j] = i;    // unordered set; order fixed by rank
}

// Fused count+scan+slot-assignment via decoupled look-back (deterministic:
// produced values are timing-independent). One pass over g_lin, 2 barriers.
// (Empirically the fastest mid-pipeline across R7..R15 variants.)
__global__ void k_scanrank(int n, float* __restrict__ o_coor) {
    __shared__ int warpTot[32];
    __shared__ int sh_off;
    int tid = threadIdx.x;
    int lane = tid & 31, w = tid >> 5;
    int bid = blockIdx.x;
    int base = bid * CHUNK + tid * 4;

    // ---- marks for 4 consecutive points ----
    int lin[4], m[4];
    int s = 0;
    if (base + 3 < n) {
        int4 l4 = *(const int4*)&g_lin[base];
        lin[0] = l4.x; lin[1] = l4.y; lin[2] = l4.z; lin[3] = l4.w;
        #pragma unroll
        for (int k = 0; k < 4; k++) {
            m[k] = (lin[k] >= 0 && g_first[lin[k]] == base + k) ? 1 : 0;
            s += m[k];
        }
    } else {
        #pragma unroll
        for (int k = 0; k < 4; k++) {
            int i = base + k;
            int l = (i < n) ? g_lin[i] : -1;
            lin[k] = l;
            m[k] = (l >= 0 && g_first[l] == i) ? 1 : 0;
            s += m[k];
        }
    }

    // ---- block scan: warp shfl scan + warp-aggregate scan (2 barriers) ----
    int inc = warpInclScan(s, lane);
    if (lane == 31) warpTot[w] = inc;
    __syncthreads();
    if (w == 0) warpTot[lane] = warpInclScan(warpTot[lane], lane);
    __syncthreads();
    int blockIncl = inc + ((w > 0) ? warpTot[w - 1] : 0);
    int total = warpTot[31];
    int ex = blockIncl - s;          // block-local exclusive prefix

    // ---- decoupled look-back (thread 0, serial walk — fastest measured) ----
    if (tid == 0) {
        if (bid == 0) {
            atomicExch(&g_desc[0], ((unsigned long long)FLAG_INC << 32) | (unsigned)total);
            sh_off = 0;
        } else {
            atomicExch(&g_desc[bid], ((unsigned long long)FLAG_AGG << 32) | (unsigned)total);
            int p = bid - 1;
            int run = 0, off;
            while (true) {
                unsigned long long d = *(volatile unsigned long long*)&g_desc[p];
                unsigned flag = (unsigned)(d >> 32);
                if (flag == FLAG_INC) { off = (int)(unsigned)d + run; break; }
                if (flag == FLAG_AGG) { run += (int)(unsigned)d; p--; }
            }
            atomicExch(&g_desc[bid], ((unsigned long long)FLAG_INC << 32) | (unsigned)(off + total));
            sh_off = off;
        }
    }
    __syncthreads();
    int off = sh_off;
    if (off >= MAXV) return;         // whole block past the slot budget (~97%)

    int r = off + ex;
    #pragma unroll
    for (int k = 0; k < 4; k++) {
        if (m[k]) {
            if (r < MAXV) {
                int c = min(g_cnt[lin[k]], CAP);
                g_vlist[r] = lin[k] | (c << 18);        // pack voxel id + clamped cnt
                int x = lin[k] % GX, y = lin[k] / GX;   // z == 0
                o_coor[r * 3 + 0] = 0.0f;
                o_coor[r * 3 + 1] = (float)y;
                o_coor[r * 3 + 2] = (float)x;
            }
            r++;
        }
    }
}

// One warp per slot. Ranks bucket entries by original point index (distinct ->
// permutation), writes point rows at their ranks, zeroes padding rows in-place
// (no global memset):
//   n==0      : all 32 rows zeroed (lanes write row==lane)
//   0<n<=32   : ranks cover [0,n); lanes >= n zero rows [n,32)
//   n>32      : 32 entries have rank < 32 -> all rows rank-written
__global__ void k_emit(const float4* __restrict__ pts,
                       float4* __restrict__ o_vox,
                       float* __restrict__ o_np) {
    int s = blockIdx.x * 8 + (threadIdx.x >> 5);
    if (s >= MAXV) return;
    int lane = threadIdx.x & 31;
    int v = g_vlist[s];
    int lin = v & 0x3FFFF;
    int n = (v >= 0) ? (v >> 18) : 0;    // clamped to CAP at pack time
    if (lane == 0) o_np[s] = (float)min(n, MAXP);
    float4* row = o_vox + (size_t)s * MAXP;
    const float4 z4 = make_float4(0.f, 0.f, 0.f, 0.f);

    if (n <= 32) {                       // common case (incl. empty slots)
        int m = n;                       // warp-uniform
        const int* buf = &g_vbuf[lin * CAP];
        int e0 = (v >= 0 && lane < m) ? buf[lane] : SENTINEL;
        int r0 = 0;
        for (int j = 0; j < m; j++) {    // m uniform across the warp
            int a = __shfl_sync(0xffffffffu, e0, j);
            r0 += (a < e0) ? 1 : 0;
        }
        if (lane < m) row[r0] = pts[e0];
        else          row[lane] = z4;    // zero padding rows [m, 32)
    } else {                             // rare: up to 64 entries, keep ranks < 32
        int m = n;                       // already min(cnt, CAP)
        const int* buf = &g_vbuf[lin * CAP];
        int e0 = (lane      < m) ? buf[lane]      : SENTINEL;
        int e1 = (lane + 32 < m) ? buf[lane + 32] : SENTINEL;
        int r0 = 0, r1 = 0;
        #pragma unroll
        for (int j = 0; j < 32; j++) {
            int a = __shfl_sync(0xffffffffu, e0, j);
            int b = __shfl_sync(0xffffffffu, e1, j);
            r0 += (a < e0) + (b < e0);
            r1 += (a < e1) + (b < e1);
        }
        if (e0 != SENTINEL && r0 < MAXP) row[r0] = pts[e0];
        if (e1 != SENTINEL && r1 < MAXP) row[r1] = pts[e1];
    }
}

// ---------------- launch ----------------
extern "C" void kernel_launch(void* const* d_in, const int* in_sizes, int n_in,
                              void* d_out, int out_size) {
    const float4* pts = (const float4*)d_in[0];
    int n = in_sizes[0] / 4;
    if (n > NPMAX) n = NPMAX;

    float* out    = (float*)d_out;
    float* o_coor = out + (size_t)MAXV * MAXP * 4;   // 5,120,000
    float* o_np   = o_coor + (size_t)MAXV * 3;       // +120,000

    int nb = (n + CHUNK - 1) / CHUNK;                // 586 for n = 2.4M

    k_init    <<<(NVOX + 255) / 256, 256>>>(o_coor);
    k_point   <<<(n + 255) / 256, 256>>>(pts, n);
    k_scanrank<<<nb, 1024>>>(n, o_coor);
    k_emit    <<<(MAXV + 7) / 8, 256>>>(pts, (float4*)out, o_np);
}